// round 9
// baseline (speedup 1.0000x reference)
#include <cuda_runtime.h>
#include <cstdint>
#include <cstddef>

// Problem constants
#define BDIM 8
#define DDIM 256
#define TDIM 8192
#define NQ 8
#define BINS 1024
#define TT 64                        // tokens per CTA
#define NB 64                        // bins per chunk
#define NCHUNK 16                    // chunks per stage
#define NG (NQ * NCHUNK)             // 128 total chunks
#define RS 260                       // padded row stride (floats)
#define NTILE ((BDIM * TDIM) / TT)   // 1024 CTAs
#define NT 512                       // threads per CTA (16 warps, 4 per SMSP)
#define QELEMS (BDIM * DDIM * TDIM)  // 16777216
#define CELEMS (NQ * BDIM * TDIM)    // 524288

// SMEM layout (float offsets)
#define OFF_R 0
#define OFF_C0 (TT * RS)             // 16640
#define OFF_C1 (2 * TT * RS)         // 33280
#define OFF_IDX (3 * TT * RS)        // 64 ints
#define OFF_RD (OFF_IDX + 64)        // 256 floats (4 bin-columns x 64 tokens)
#define OFF_RI (OFF_RD + 256)        // 256 ints
#define OFF_WD (OFF_RI + 256)        // 16 doubles
#define OFF_FLAG (OFF_WD + 32)
#define SMEM_FLOATS (OFF_FLAG + 8)
#define SMEM_BYTES (SMEM_FLOATS * 4) // ~202 KB

__device__ float    g_cbsq[NQ * BINS];
__device__ double   g_losspart[NTILE];
__device__ unsigned g_ctr;

// ---------------------------------------------------------------------------
// Precompute ||c||^2 per codebook row. One warp per bin.
// ---------------------------------------------------------------------------
__global__ void cbsq_kernel(const float* __restrict__ cbs) {
    int gid  = blockIdx.x * blockDim.x + threadIdx.x;
    int w    = gid >> 5;
    int lane = gid & 31;
    const float* row = cbs + (size_t)w * DDIM;
    float s = 0.f;
#pragma unroll
    for (int k = 0; k < DDIM; k += 32) {
        float v = row[k + lane];
        s = fmaf(v, v, s);
    }
#pragma unroll
    for (int o = 16; o; o >>= 1) s += __shfl_xor_sync(0xffffffffu, s, o);
    if (lane == 0) g_cbsq[w] = s;
}

// ---------------------------------------------------------------------------
// Async prefetch of one 64-bin codebook chunk into SMEM (row-padded to RS).
// 512 threads, 8 x 16B each.
// ---------------------------------------------------------------------------
__device__ __forceinline__ void prefetch_chunk(const float* __restrict__ cbs,
                                               int g, float* __restrict__ sCbuf,
                                               int tid) {
    int s = g >> 4, c = g & 15;
    const float* src = cbs + (size_t)(s * BINS + c * NB) * DDIM;
    unsigned dstbase = (unsigned)__cvta_generic_to_shared(sCbuf);
#pragma unroll
    for (int it = 0; it < 8; ++it) {
        int f   = tid + it * NT;    // float4 index, 0..4095
        int row = f >> 6;           // bin row 0..63
        int c4  = f & 63;           // float4 within row
        unsigned     dst = dstbase + (unsigned)((row * RS + c4 * 4) * 4);
        const float* gp  = src + row * DDIM + c4 * 4;
        asm volatile("cp.async.cg.shared.global [%0], [%1], 16;\n" ::"r"(dst), "l"(gp));
    }
    asm volatile("cp.async.commit_group;\n");
}

// non-volatile: pure computation, ptxas may schedule freely
#define FMA2(d, a, b) \
    asm("fma.rn.f32x2 %0, %1, %2, %0;" : "+l"(d) : "l"(a), "l"(b))

// ---------------------------------------------------------------------------
// Fused RVQ kernel. One CTA = 64 tokens, 512 threads (4 warps/SMSP).
// Thread tile: 2 tok x 4 bins, dual-chain f32x2 accumulators.
// Warp = 16 tok x 16 bins; warps arranged 4x4 over the 64x64 chunk:
//   wty = w>>2 (token block), wtx = w&3 (bin block).
//   lane: lty = l>>2 (0..7), ltx = l&3 (0..3).
//   thread tokens = wty*16 + lty + {0,8};  bins = wtx*16 + ltx + {0,4,8,12}.
// Live regs ~95 < 128 (hard cap at 512 thr) -> no spill.
// ---------------------------------------------------------------------------
__global__ __launch_bounds__(NT, 1) void rvq_main(const float* __restrict__ x,
                                                  const float* __restrict__ cbs,
                                                  const int* __restrict__ srp,
                                                  float* __restrict__ out) {
    extern __shared__ float sm[];
    float*  sR   = sm + OFF_R;
    int*    sIdx = (int*)(sm + OFF_IDX);
    float*  sRd  = sm + OFF_RD;
    int*    sRi  = (int*)(sm + OFF_RI);
    double* sWD  = (double*)(sm + OFF_WD);
    int*    sFlg = (int*)(sm + OFF_FLAG);

    const int tid = threadIdx.x;
    const int w   = tid >> 5;   // 0..15
    const int l   = tid & 31;
    const int wty = w >> 2;     // 0..3 token block (16 tokens)
    const int wtx = w & 3;      // 0..3 bin block (16 bins)
    const int lty = l >> 2;     // 0..7
    const int ltx = l & 3;      // 0..3
    const int b   = blockIdx.x >> 7;
    const int t0  = (blockIdx.x & 127) * TT;

    float* out_q = out;
    float* out_c = out + QELEMS;

    // ---- prologue: load + transpose x tile into sR[t][k] ----
#pragma unroll
    for (int it = 0; it < 8; ++it) {
        int f  = tid + it * NT;
        int k  = f >> 4;
        int t4 = f & 15;
        float4 v = *(const float4*)(x + (size_t)(b * DDIM + k) * TDIM + t0 + t4 * 4);
        int tl = t4 * 4;
        sR[(tl + 0) * RS + k] = v.x;
        sR[(tl + 1) * RS + k] = v.y;
        sR[(tl + 2) * RS + k] = v.z;
        sR[(tl + 3) * RS + k] = v.w;
    }
    prefetch_chunk(cbs, 0, sm + OFF_C0, tid);

    double lossLocal = 0.0;
    const int    tb = wty * 16 + lty;       // thread tokens: tb, tb+8
    const float* Rb = sR + tb * RS;

    for (int s = 0; s < NQ; ++s) {
        float bd[2] = {3.4e38f, 3.4e38f};
        int   bi[2] = {0, 0};

        for (int c = 0; c < NCHUNK; ++c) {
            int g = s * NCHUNK + c;
            const float* sC = sm + ((g & 1) ? OFF_C1 : OFF_C0);

            asm volatile("cp.async.wait_group 0;\n");
            __syncthreads();   // chunk g visible; all threads done with other buffer

            if (g + 1 < NG)
                prefetch_chunk(cbs, g + 1, sm + ((g & 1) ? OFF_C0 : OFF_C1), tid);

            const float* Cb = sC + (wtx * 16 + ltx) * RS;   // bins +4j

            // dual-chain f32x2 accumulators per (tok i, bin j)
            ulonglong2 acc[2][4];
#pragma unroll
            for (int i = 0; i < 2; ++i)
#pragma unroll
                for (int j = 0; j < 4; ++j) { acc[i][j].x = 0ull; acc[i][j].y = 0ull; }

#pragma unroll 2
            for (int k4 = 0; k4 < DDIM; k4 += 4) {
                ulonglong2 cc[4];
#pragma unroll
                for (int j = 0; j < 4; ++j)
                    cc[j] = *(const ulonglong2*)(Cb + (j * 4) * RS + k4);
                ulonglong2 r0 = *(const ulonglong2*)(Rb + k4);
                ulonglong2 r1 = *(const ulonglong2*)(Rb + 8 * RS + k4);
#pragma unroll
                for (int j = 0; j < 4; ++j) {
                    FMA2(acc[0][j].x, r0.x, cc[j].x);
                    FMA2(acc[0][j].y, r0.y, cc[j].y);
                }
#pragma unroll
                for (int j = 0; j < 4; ++j) {
                    FMA2(acc[1][j].x, r1.x, cc[j].x);
                    FMA2(acc[1][j].y, r1.y, cc[j].y);
                }
            }

            // ---- distances + running argmin (j ascending = bins ascending) ----
            const float* csq = &g_cbsq[s * BINS + c * NB];
#pragma unroll
            for (int i = 0; i < 2; ++i)
#pragma unroll
                for (int j = 0; j < 4; ++j) {
                    float ax, ay, bx, by;
                    asm("mov.b64 {%0,%1}, %2;" : "=f"(ax), "=f"(ay) : "l"(acc[i][j].x));
                    asm("mov.b64 {%0,%1}, %2;" : "=f"(bx), "=f"(by) : "l"(acc[i][j].y));
                    float dot  = (ax + ay) + (bx + by);
                    int   binl = wtx * 16 + ltx + j * 4;
                    float dist = fmaf(-2.f, dot, __ldg(csq + binl));
                    if (dist < bd[i]) { bd[i] = dist; bi[i] = c * NB + binl; }
                }
        }

        // ---- lexicographic reduce over the 4 ltx lanes ----
#pragma unroll
        for (int o = 1; o < 4; o <<= 1) {
#pragma unroll
            for (int i = 0; i < 2; ++i) {
                float od = __shfl_xor_sync(0xffffffffu, bd[i], o);
                int   oi = __shfl_xor_sync(0xffffffffu, bi[i], o);
                if (od < bd[i] || (od == bd[i] && oi < bi[i])) { bd[i] = od; bi[i] = oi; }
            }
        }
        if (ltx == 0) {
            sRd[wtx * 64 + tb]     = bd[0];  sRi[wtx * 64 + tb]     = bi[0];
            sRd[wtx * 64 + tb + 8] = bd[1];  sRi[wtx * 64 + tb + 8] = bi[1];
        }
        __syncthreads();

        // ---- reduce across the 4 bin-columns; write codes ----
        if (tid < TT) {
            float d   = sRd[tid];
            int   idx = sRi[tid];
#pragma unroll
            for (int ww = 1; ww < 4; ++ww) {
                float dw = sRd[ww * 64 + tid];
                int   iw = sRi[ww * 64 + tid];
                if (dw < d || (dw == d && iw < idx)) { d = dw; idx = iw; }
            }
            sIdx[tid] = idx;
            out_c[(size_t)(s * BDIM + b) * TDIM + t0 + tid] = (float)idx;
        }
        __syncthreads();

        // ---- residual update + commitment loss (thread = 1/8 token) ----
        {
            int t   = tid >> 3;
            int ko  = (tid & 7) * 32;
            int idx = sIdx[t];
            const float4* cv = (const float4*)(cbs + (size_t)(s * BINS + idx) * DDIM + ko);
            float* rp = sR + t * RS + ko;
            float  lsum = 0.f;
#pragma unroll
            for (int q = 0; q < 8; ++q) {
                float4 v  = cv[q];
                float a0 = rp[q * 4 + 0] - v.x;
                float a1 = rp[q * 4 + 1] - v.y;
                float a2 = rp[q * 4 + 2] - v.z;
                float a3 = rp[q * 4 + 3] - v.w;
                rp[q * 4 + 0] = a0; rp[q * 4 + 1] = a1;
                rp[q * 4 + 2] = a2; rp[q * 4 + 3] = a3;
                lsum += a0 * a0 + a1 * a1 + a2 * a2 + a3 * a3;
            }
            lossLocal += (double)lsum;
        }
        // next chunk-loop top sync orders sR writes before GEMM reads
    }
    __syncthreads();

    // ---- epilogue: quantized = x - final residual ----
#pragma unroll
    for (int it = 0; it < 8; ++it) {
        int f  = tid + it * NT;
        int k  = f >> 4;
        int t4 = f & 15;
        const float4 v = *(const float4*)(x + (size_t)(b * DDIM + k) * TDIM + t0 + t4 * 4);
        int tl = t4 * 4;
        float4 o;
        o.x = v.x - sR[(tl + 0) * RS + k];
        o.y = v.y - sR[(tl + 1) * RS + k];
        o.z = v.z - sR[(tl + 2) * RS + k];
        o.w = v.w - sR[(tl + 3) * RS + k];
        *(float4*)(out_q + (size_t)(b * DDIM + k) * TDIM + t0 + t4 * 4) = o;
    }

    // ---- per-CTA loss partial (deterministic) ----
#pragma unroll
    for (int o = 16; o; o >>= 1) lossLocal += __shfl_down_sync(0xffffffffu, lossLocal, o);
    if (l == 0) sWD[w] = lossLocal;
    __syncthreads();
    if (tid == 0) {
        double t = 0.0;
#pragma unroll
        for (int i = 0; i < 16; ++i) t += sWD[i];
        g_losspart[blockIdx.x] = t;
        __threadfence();
        unsigned old = atomicAdd(&g_ctr, 1u);
        *sFlg = (old == NTILE - 1) ? 1 : 0;
    }
    __syncthreads();

    // ---- last CTA finalizes scalars (fixed-order, deterministic) ----
    if (*sFlg && tid < 32) {
        __threadfence();
        double ssum = 0.0;
        for (int i = l; i < NTILE; i += 32) ssum += __ldcg(&g_losspart[i]);
#pragma unroll
        for (int o = 16; o; o >>= 1) ssum += __shfl_down_sync(0xffffffffu, ssum, o);
        if (l == 0) {
            int   iv = *srp;
            float fv = __int_as_float(iv);
            double sr = (iv > 0 && iv < 100000000) ? (double)iv : (double)fv;
            out[QELEMS + CELEMS]     = (float)((double)NQ * 10.0 * sr / 1000.0);
            out[QELEMS + CELEMS + 1] = (float)(ssum / (4.0 * (double)NQ * (double)QELEMS));
            atomicExch(&g_ctr, 0u);   // reset for next graph replay
        }
    }
}

// ---------------------------------------------------------------------------
extern "C" void kernel_launch(void* const* d_in, const int* in_sizes, int n_in,
                              void* d_out, int out_size) {
    const float* x   = nullptr;
    const float* cbs = nullptr;
    const int*   srp = nullptr;
    for (int i = 0; i < n_in; ++i) {
        if (in_sizes[i] == QELEMS)                x   = (const float*)d_in[i];
        else if (in_sizes[i] == NQ * BINS * DDIM) cbs = (const float*)d_in[i];
        else                                      srp = (const int*)d_in[i];
    }
    float* out = (float*)d_out;

    cudaFuncSetAttribute(rvq_main, cudaFuncAttributeMaxDynamicSharedMemorySize, SMEM_BYTES);

    cbsq_kernel<<<(NQ * BINS * 32) / 256, 256>>>(cbs);
    rvq_main<<<NTILE, NT, SMEM_BYTES>>>(x, cbs, srp, out);
}

// round 11
// speedup vs baseline: 1.3748x; 1.3748x over previous
#include <cuda_runtime.h>
#include <cstdint>
#include <cstddef>

// Problem constants
#define BDIM 8
#define DDIM 256
#define TDIM 8192
#define NQ 8
#define BINS 1024
#define TT 64                        // tokens per CTA
#define NB 64                        // bins per chunk
#define NCHUNK 16                    // chunks per stage
#define NG (NQ * NCHUNK)             // 128 total chunks
#define RS 260                       // padded row stride (floats)
#define NTILE ((BDIM * TDIM) / TT)   // 1024 CTAs
#define NT 256                       // threads per CTA (8 warps, 2 per SMSP)
#define QELEMS (BDIM * DDIM * TDIM)  // 16777216
#define CELEMS (NQ * BDIM * TDIM)    // 524288

// SMEM layout (float offsets)
#define OFF_R 0
#define OFF_C0 (TT * RS)             // 16640
#define OFF_C1 (2 * TT * RS)         // 33280
#define OFF_IDX (3 * TT * RS)        // 64 ints
#define OFF_RD (OFF_IDX + 64)        // 128 floats (2 bin-columns x 64 tokens)
#define OFF_RI (OFF_RD + 128)        // 128 ints
#define OFF_WD (OFF_RI + 128)        // 8 doubles
#define OFF_FLAG (OFF_WD + 16)
#define SMEM_FLOATS (OFF_FLAG + 8)
#define SMEM_BYTES (SMEM_FLOATS * 4) // ~200.5 KB

__device__ float    g_cbsq[NQ * BINS];
__device__ double   g_losspart[NTILE];
__device__ unsigned g_ctr;

// ---------------------------------------------------------------------------
// Precompute ||c||^2 per codebook row. One warp per bin.
// ---------------------------------------------------------------------------
__global__ void cbsq_kernel(const float* __restrict__ cbs) {
    int gid  = blockIdx.x * blockDim.x + threadIdx.x;
    int w    = gid >> 5;
    int lane = gid & 31;
    const float* row = cbs + (size_t)w * DDIM;
    float s = 0.f;
#pragma unroll
    for (int k = 0; k < DDIM; k += 32) {
        float v = row[k + lane];
        s = fmaf(v, v, s);
    }
#pragma unroll
    for (int o = 16; o; o >>= 1) s += __shfl_xor_sync(0xffffffffu, s, o);
    if (lane == 0) g_cbsq[w] = s;
}

// ---------------------------------------------------------------------------
// Async prefetch of one 64-bin codebook chunk into SMEM (row-padded to RS).
// 256 threads, 16 x 16B each.
// ---------------------------------------------------------------------------
__device__ __forceinline__ void prefetch_chunk(const float* __restrict__ cbs,
                                               int g, float* __restrict__ sCbuf,
                                               int tid) {
    int s = g >> 4, c = g & 15;
    const float* src = cbs + (size_t)(s * BINS + c * NB) * DDIM;
    unsigned dstbase = (unsigned)__cvta_generic_to_shared(sCbuf);
#pragma unroll
    for (int it = 0; it < 16; ++it) {
        int f   = tid + it * NT;    // float4 index, 0..4095
        int row = f >> 6;           // bin row 0..63
        int c4  = f & 63;           // float4 within row
        unsigned     dst = dstbase + (unsigned)((row * RS + c4 * 4) * 4);
        const float* gp  = src + row * DDIM + c4 * 4;
        asm volatile("cp.async.cg.shared.global [%0], [%1], 16;\n" ::"r"(dst), "l"(gp));
    }
    asm volatile("cp.async.commit_group;\n");
}

// non-volatile: pure computation, ptxas may schedule freely
#define FMA2(d, a, b) \
    asm("fma.rn.f32x2 %0, %1, %2, %0;" : "+l"(d) : "l"(a), "l"(b))

// ---------------------------------------------------------------------------
// Fused RVQ kernel. One CTA = 64 tokens, 256 threads (8 warps, 2 per SMSP —
// the empirically best point from rounds 1..9).
// Thread tile: 4 tok x 4 bins, dual-chain f32x2 accumulators (64 acc regs).
// Warp = 16 tok x 32 bins; 8 warps arranged 4 (token) x 2 (bin):
//   wty = w>>1 (0..3) token block, wtx = w&1 (0..1) bin block.
//   lane: lty = l>>3 (0..3), ltx = l&7 (0..7).
//   thread tokens = wty*16 + lty + {0,4,8,12}   (r-load banks 0/4/8/12: clean)
//   thread bins   = wtx*32 + ltx + {0,8,16,24}  (cc-load covers all 32 banks)
// LDS per k4 = 8 per 32 FFMA2 (vs 10 in R1, 6/16 in R9).
// ---------------------------------------------------------------------------
__global__ __launch_bounds__(NT) void rvq_main(const float* __restrict__ x,
                                               const float* __restrict__ cbs,
                                               const int* __restrict__ srp,
                                               float* __restrict__ out) {
    extern __shared__ float sm[];
    float*  sR   = sm + OFF_R;
    int*    sIdx = (int*)(sm + OFF_IDX);
    float*  sRd  = sm + OFF_RD;
    int*    sRi  = (int*)(sm + OFF_RI);
    double* sWD  = (double*)(sm + OFF_WD);
    int*    sFlg = (int*)(sm + OFF_FLAG);

    const int tid = threadIdx.x;
    const int w   = tid >> 5;   // 0..7
    const int l   = tid & 31;
    const int wty = w >> 1;     // 0..3 token block (16 tokens)
    const int wtx = w & 1;      // 0..1 bin block (32 bins)
    const int lty = l >> 3;     // 0..3
    const int ltx = l & 7;      // 0..7
    const int b   = blockIdx.x >> 7;
    const int t0  = (blockIdx.x & 127) * TT;

    float* out_q = out;
    float* out_c = out + QELEMS;

    // ---- prologue: load + transpose x tile into sR[t][k] ----
#pragma unroll
    for (int it = 0; it < 16; ++it) {
        int f  = tid + it * NT;
        int k  = f >> 4;
        int t4 = f & 15;
        float4 v = *(const float4*)(x + (size_t)(b * DDIM + k) * TDIM + t0 + t4 * 4);
        int tl = t4 * 4;
        sR[(tl + 0) * RS + k] = v.x;
        sR[(tl + 1) * RS + k] = v.y;
        sR[(tl + 2) * RS + k] = v.z;
        sR[(tl + 3) * RS + k] = v.w;
    }
    prefetch_chunk(cbs, 0, sm + OFF_C0, tid);

    double lossLocal = 0.0;
    const int    tb = wty * 16 + lty;       // thread tokens: tb + 4i
    const float* Rb = sR + tb * RS;

    for (int s = 0; s < NQ; ++s) {
        float bd[4];
        int   bi[4];
#pragma unroll
        for (int i = 0; i < 4; ++i) { bd[i] = 3.4e38f; bi[i] = 0; }

        for (int c = 0; c < NCHUNK; ++c) {
            int g = s * NCHUNK + c;
            const float* sC = sm + ((g & 1) ? OFF_C1 : OFF_C0);

            asm volatile("cp.async.wait_group 0;\n");
            __syncthreads();   // chunk g visible; all threads done with other buffer

            if (g + 1 < NG)
                prefetch_chunk(cbs, g + 1, sm + ((g & 1) ? OFF_C0 : OFF_C1), tid);

            const float* Cb = sC + (wtx * 32 + ltx) * RS;   // bins +8j

            // dual-chain f32x2 accumulators per (tok i, bin j): 64 regs
            ulonglong2 acc[4][4];
#pragma unroll
            for (int i = 0; i < 4; ++i)
#pragma unroll
                for (int j = 0; j < 4; ++j) { acc[i][j].x = 0ull; acc[i][j].y = 0ull; }

#pragma unroll 4
            for (int k4 = 0; k4 < DDIM; k4 += 4) {
                ulonglong2 cc[4];
#pragma unroll
                for (int j = 0; j < 4; ++j)
                    cc[j] = *(const ulonglong2*)(Cb + (j * 8) * RS + k4);
#pragma unroll
                for (int i = 0; i < 4; ++i) {
                    ulonglong2 r = *(const ulonglong2*)(Rb + (i * 4) * RS + k4);
#pragma unroll
                    for (int j = 0; j < 4; ++j) {
                        FMA2(acc[i][j].x, r.x, cc[j].x);
                        FMA2(acc[i][j].y, r.y, cc[j].y);
                    }
                }
            }

            // ---- distances + running argmin (j ascending = bins ascending) ----
            const float* csq = &g_cbsq[s * BINS + c * NB];
#pragma unroll
            for (int i = 0; i < 4; ++i)
#pragma unroll
                for (int j = 0; j < 4; ++j) {
                    float ax, ay, bx, by;
                    asm("mov.b64 {%0,%1}, %2;" : "=f"(ax), "=f"(ay) : "l"(acc[i][j].x));
                    asm("mov.b64 {%0,%1}, %2;" : "=f"(bx), "=f"(by) : "l"(acc[i][j].y));
                    float dot  = (ax + ay) + (bx + by);
                    int   binl = wtx * 32 + ltx + j * 8;
                    float dist = fmaf(-2.f, dot, __ldg(csq + binl));
                    if (dist < bd[i]) { bd[i] = dist; bi[i] = c * NB + binl; }
                }
        }

        // ---- lexicographic reduce over the 8 ltx lanes (xor on low 3 bits) ----
#pragma unroll
        for (int o = 1; o < 8; o <<= 1) {
#pragma unroll
            for (int i = 0; i < 4; ++i) {
                float od = __shfl_xor_sync(0xffffffffu, bd[i], o);
                int   oi = __shfl_xor_sync(0xffffffffu, bi[i], o);
                if (od < bd[i] || (od == bd[i] && oi < bi[i])) { bd[i] = od; bi[i] = oi; }
            }
        }
        if (ltx == 0) {
#pragma unroll
            for (int i = 0; i < 4; ++i) {
                sRd[wtx * 64 + tb + 4 * i] = bd[i];
                sRi[wtx * 64 + tb + 4 * i] = bi[i];
            }
        }
        __syncthreads();

        // ---- reduce across the 2 bin-columns; write codes ----
        if (tid < TT) {
            float d0 = sRd[tid],      d1 = sRd[64 + tid];
            int   i0 = sRi[tid],      i1 = sRi[64 + tid];
            int idx = (d1 < d0 || (d1 == d0 && i1 < i0)) ? i1 : i0;
            sIdx[tid] = idx;
            out_c[(size_t)(s * BDIM + b) * TDIM + t0 + tid] = (float)idx;
        }
        __syncthreads();

        // ---- residual update + commitment loss (thread = 1/4 token) ----
        {
            int t   = tid >> 2;
            int ko  = (tid & 3) * 64;
            int idx = sIdx[t];
            const float4* cv = (const float4*)(cbs + (size_t)(s * BINS + idx) * DDIM + ko);
            float* rp = sR + t * RS + ko;
            float  lsum = 0.f;
#pragma unroll
            for (int q = 0; q < 16; ++q) {
                float4 v  = cv[q];
                float a0 = rp[q * 4 + 0] - v.x;
                float a1 = rp[q * 4 + 1] - v.y;
                float a2 = rp[q * 4 + 2] - v.z;
                float a3 = rp[q * 4 + 3] - v.w;
                rp[q * 4 + 0] = a0; rp[q * 4 + 1] = a1;
                rp[q * 4 + 2] = a2; rp[q * 4 + 3] = a3;
                lsum += a0 * a0 + a1 * a1 + a2 * a2 + a3 * a3;
            }
            lossLocal += (double)lsum;
        }
        // next chunk-loop top sync orders sR writes before GEMM reads
    }
    __syncthreads();

    // ---- epilogue: quantized = x - final residual ----
#pragma unroll
    for (int it = 0; it < 16; ++it) {
        int f  = tid + it * NT;
        int k  = f >> 4;
        int t4 = f & 15;
        const float4 v = *(const float4*)(x + (size_t)(b * DDIM + k) * TDIM + t0 + t4 * 4);
        int tl = t4 * 4;
        float4 o;
        o.x = v.x - sR[(tl + 0) * RS + k];
        o.y = v.y - sR[(tl + 1) * RS + k];
        o.z = v.z - sR[(tl + 2) * RS + k];
        o.w = v.w - sR[(tl + 3) * RS + k];
        *(float4*)(out_q + (size_t)(b * DDIM + k) * TDIM + t0 + t4 * 4) = o;
    }

    // ---- per-CTA loss partial (deterministic) ----
#pragma unroll
    for (int o = 16; o; o >>= 1) lossLocal += __shfl_down_sync(0xffffffffu, lossLocal, o);
    if (l == 0) sWD[w] = lossLocal;
    __syncthreads();
    if (tid == 0) {
        double t = 0.0;
#pragma unroll
        for (int i = 0; i < 8; ++i) t += sWD[i];
        g_losspart[blockIdx.x] = t;
        __threadfence();
        unsigned old = atomicAdd(&g_ctr, 1u);
        *sFlg = (old == NTILE - 1) ? 1 : 0;
    }
    __syncthreads();

    // ---- last CTA finalizes scalars (fixed-order, deterministic) ----
    if (*sFlg && tid < 32) {
        __threadfence();
        double ssum = 0.0;
        for (int i = l; i < NTILE; i += 32) ssum += __ldcg(&g_losspart[i]);
#pragma unroll
        for (int o = 16; o; o >>= 1) ssum += __shfl_down_sync(0xffffffffu, ssum, o);
        if (l == 0) {
            int   iv = *srp;
            float fv = __int_as_float(iv);
            double sr = (iv > 0 && iv < 100000000) ? (double)iv : (double)fv;
            out[QELEMS + CELEMS]     = (float)((double)NQ * 10.0 * sr / 1000.0);
            out[QELEMS + CELEMS + 1] = (float)(ssum / (4.0 * (double)NQ * (double)QELEMS));
            atomicExch(&g_ctr, 0u);   // reset for next graph replay
        }
    }
}

// ---------------------------------------------------------------------------
extern "C" void kernel_launch(void* const* d_in, const int* in_sizes, int n_in,
                              void* d_out, int out_size) {
    const float* x   = nullptr;
    const float* cbs = nullptr;
    const int*   srp = nullptr;
    for (int i = 0; i < n_in; ++i) {
        if (in_sizes[i] == QELEMS)                x   = (const float*)d_in[i];
        else if (in_sizes[i] == NQ * BINS * DDIM) cbs = (const float*)d_in[i];
        else                                      srp = (const int*)d_in[i];
    }
    float* out = (float*)d_out;

    cudaFuncSetAttribute(rvq_main, cudaFuncAttributeMaxDynamicSharedMemorySize, SMEM_BYTES);

    cbsq_kernel<<<(NQ * BINS * 32) / 256, 256>>>(cbs);
    rvq_main<<<NTILE, NT, SMEM_BYTES>>>(x, cbs, srp, out);
}

// round 17
// speedup vs baseline: 2.0912x; 1.5211x over previous
#include <cuda_runtime.h>
#include <cuda_bf16.h>
#include <cstdint>
#include <cstddef>

// Problem constants
#define BDIM 8
#define DDIM 256
#define TDIM 8192
#define NQ 8
#define BINS 1024
#define TT 64                        // tokens per CTA
#define NBIN 32                      // bins per chunk
#define NCH 32                       // chunks per stage
#define NG2 (NQ * NCH)               // 256 chunks total
#define NTILE ((BDIM * TDIM) / TT)   // 1024 CTAs
#define NT 256
#define QELEMS (BDIM * DDIM * TDIM)
#define CELEMS (NQ * BDIM * TDIM)

// A planes: [64 tok][256 k] bf16, row padded to 528 B (33*16; banks 0,4,..28)
#define ARS 528
#define APLANE (TT * ARS)            // 33792 B
// B planes: [256 k][32 bin] bf16, row padded to 80 B (banks 0,20,8,28,16,4,24,12)
#define BRS 80
#define BPLANE (DDIM * BRS)          // 20480 B
#define CHUNKB (3 * BPLANE)          // 61440 B

// SMEM layout (bytes)
#define OFF_A 0
#define OFF_B0 (3 * APLANE)          // 101376
#define OFF_B1 (OFF_B0 + CHUNKB)     // 162816
#define OFF_IDX (OFF_B1 + CHUNKB)    // 224256: 64 ints
#define OFF_RD (OFF_IDX + 256)       // 128 floats
#define OFF_RI (OFF_RD + 512)        // 128 ints
#define OFF_WD (OFF_RI + 512)        // 8 doubles
#define OFF_FLG (OFF_WD + 64)
#define SMEM_BYTES (OFF_FLG + 64)    // ~225.7 KB

__device__ float    g_cbsq[NQ * BINS];
__device__ double   g_losspart[NTILE];
__device__ unsigned g_ctr;
__device__ __align__(16) unsigned char g_bplanes[NG2 * CHUNKB]; // 15.7 MB

// ---------------------------------------------------------------------------
__device__ __forceinline__ uint32_t smem_u32(const void* p) {
    uint32_t a;
    asm("{ .reg .u64 t; cvta.to.shared.u64 t, %1; cvt.u32.u64 %0, t; }" : "=r"(a) : "l"(p));
    return a;
}
#define LDSM4(r, addr)                                                         \
    asm volatile("ldmatrix.sync.aligned.m8n8.x4.shared.b16 {%0,%1,%2,%3}, [%4];" \
        : "=r"((r)[0]), "=r"((r)[1]), "=r"((r)[2]), "=r"((r)[3]) : "r"(addr))
#define LDSM4T(r, addr)                                                        \
    asm volatile("ldmatrix.sync.aligned.m8n8.x4.trans.shared.b16 {%0,%1,%2,%3}, [%4];" \
        : "=r"((r)[0]), "=r"((r)[1]), "=r"((r)[2]), "=r"((r)[3]) : "r"(addr))
#define MMA(d, a, bb0, bb1)                                                    \
    asm volatile("mma.sync.aligned.m16n8k16.row.col.f32.bf16.bf16.f32 "        \
        "{%0,%1,%2,%3}, {%4,%5,%6,%7}, {%8,%9}, {%0,%1,%2,%3};"                \
        : "+f"((d)[0]), "+f"((d)[1]), "+f"((d)[2]), "+f"((d)[3])               \
        : "r"((a)[0]), "r"((a)[1]), "r"((a)[2]), "r"((a)[3]), "r"(bb0), "r"(bb1))

__device__ __forceinline__ void split3s(float v, __nv_bfloat16& h0,
                                        __nv_bfloat16& h1, __nv_bfloat16& h2) {
    h0 = __float2bfloat16_rn(v); float r = v - __bfloat162float(h0);
    h1 = __float2bfloat16_rn(r); r -= __bfloat162float(h1);
    h2 = __float2bfloat16_rn(r);
}
__device__ __forceinline__ float bflo(uint32_t u) {
    return __bfloat162float(__ushort_as_bfloat16((unsigned short)(u & 0xffff)));
}
__device__ __forceinline__ float bfhi(uint32_t u) {
    return __bfloat162float(__ushort_as_bfloat16((unsigned short)(u >> 16)));
}

// ---------------------------------------------------------------------------
// cbsq: exact fp32 ||c||^2 (one warp per bin)
// ---------------------------------------------------------------------------
__global__ void cbsq_kernel(const float* __restrict__ cbs) {
    int gid = blockIdx.x * blockDim.x + threadIdx.x;
    int w = gid >> 5, lane = gid & 31;
    const float* row = cbs + (size_t)w * DDIM;
    float s = 0.f;
#pragma unroll
    for (int k = 0; k < DDIM; k += 32) { float v = row[k + lane]; s = fmaf(v, v, s); }
#pragma unroll
    for (int o = 16; o; o >>= 1) s += __shfl_xor_sync(0xffffffffu, s, o);
    if (lane == 0) g_cbsq[w] = s;
}

// ---------------------------------------------------------------------------
// prep: codebook -> 3 bf16 planes, k-major [k][bin] padded rows, per chunk.
// block = chunk g, thread = k row. Coalesced reads, contiguous 64B row writes.
// ---------------------------------------------------------------------------
__global__ void prep_kernel(const float* __restrict__ cbs) {
    int g = blockIdx.x;          // 0..255
    int k = threadIdx.x;         // 0..255
    int s = g >> 5, c = g & 31;
    float v[32];
#pragma unroll
    for (int b = 0; b < 32; ++b)
        v[b] = __ldg(cbs + ((size_t)(s * BINS + c * NBIN + b)) * DDIM + k);
    unsigned char* dst = g_bplanes + (size_t)g * CHUNKB + k * BRS;
    float r1[32];
#pragma unroll
    for (int j = 0; j < 16; ++j) {
        __nv_bfloat16 h0 = __float2bfloat16_rn(v[2 * j]);
        __nv_bfloat16 h1 = __float2bfloat16_rn(v[2 * j + 1]);
        r1[2 * j] = v[2 * j] - __bfloat162float(h0);
        r1[2 * j + 1] = v[2 * j + 1] - __bfloat162float(h1);
        *(uint32_t*)(dst + j * 4) =
            (uint32_t)__bfloat16_as_ushort(h0) | ((uint32_t)__bfloat16_as_ushort(h1) << 16);
    }
#pragma unroll
    for (int j = 0; j < 16; ++j) {
        __nv_bfloat16 h0 = __float2bfloat16_rn(r1[2 * j]);
        __nv_bfloat16 h1 = __float2bfloat16_rn(r1[2 * j + 1]);
        float r2a = r1[2 * j] - __bfloat162float(h0);
        float r2b = r1[2 * j + 1] - __bfloat162float(h1);
        *(uint32_t*)(dst + BPLANE + j * 4) =
            (uint32_t)__bfloat16_as_ushort(h0) | ((uint32_t)__bfloat16_as_ushort(h1) << 16);
        __nv_bfloat16 g0 = __float2bfloat16_rn(r2a);
        __nv_bfloat16 g1 = __float2bfloat16_rn(r2b);
        *(uint32_t*)(dst + 2 * BPLANE + j * 4) =
            (uint32_t)__bfloat16_as_ushort(g0) | ((uint32_t)__bfloat16_as_ushort(g1) << 16);
    }
}

// ---------------------------------------------------------------------------
__device__ __forceinline__ void prefetch_chunk(int g, uint32_t dst, int tid) {
    const unsigned char* src = g_bplanes + (size_t)g * CHUNKB;
#pragma unroll
    for (int it = 0; it < 15; ++it) {          // 15*256*16 = 61440
        int off = (tid + it * 256) * 16;
        asm volatile("cp.async.cg.shared.global [%0], [%1], 16;\n"
                     :: "r"(dst + off), "l"(src + off));
    }
    asm volatile("cp.async.commit_group;\n");
}

// ---------------------------------------------------------------------------
// Fused RVQ, HMMA edition. CTA = 64 tokens, 256 threads.
// Warp tile 16 tok x 16 bins; warps 4 (token) x 2 (bin). 6-term bf16 split
// GEMM via mma.m16n8k16, fp32 accumulator fragments (deterministic order).
// ---------------------------------------------------------------------------
__global__ __launch_bounds__(NT) void rvq_main(const float* __restrict__ x,
                                               const float* __restrict__ cbs,
                                               const int* __restrict__ srp,
                                               float* __restrict__ out) {
    extern __shared__ unsigned char smraw[];
    const uint32_t smb = smem_u32(smraw);
    int*    sIdx = (int*)(smraw + OFF_IDX);
    float*  sRd  = (float*)(smraw + OFF_RD);
    int*    sRi  = (int*)(smraw + OFF_RI);
    double* sWD  = (double*)(smraw + OFF_WD);
    int*    sFlg = (int*)(smraw + OFF_FLG);

    const int tid = threadIdx.x;
    const int w   = tid >> 5;
    const int l   = tid & 31;
    const int wty = w >> 1;      // 0..3 token block (16)
    const int wtx = w & 1;       // 0..1 bin block (16)
    const int b   = blockIdx.x >> 7;
    const int t0  = (blockIdx.x & 127) * TT;

    float* out_q = out;
    float* out_c = out + QELEMS;

    prefetch_chunk(0, smb + OFF_B0, tid);

    // ---- prologue: split x tile into 3 bf16 A planes [tok][k] ----
#pragma unroll
    for (int it = 0; it < 16; ++it) {
        int f  = tid + it * NT;
        int k  = f >> 4;
        int t4 = f & 15;
        float4 v = *(const float4*)(x + (size_t)(b * DDIM + k) * TDIM + t0 + t4 * 4);
        float vv[4] = {v.x, v.y, v.z, v.w};
#pragma unroll
        for (int j = 0; j < 4; ++j) {
            int tok = t4 * 4 + j;
            __nv_bfloat16 h0, h1, h2;
            split3s(vv[j], h0, h1, h2);
            *(__nv_bfloat16*)(smraw + OFF_A + 0 * APLANE + tok * ARS + k * 2) = h0;
            *(__nv_bfloat16*)(smraw + OFF_A + 1 * APLANE + tok * ARS + k * 2) = h1;
            *(__nv_bfloat16*)(smraw + OFF_A + 2 * APLANE + tok * ARS + k * 2) = h2;
        }
    }

    // ldmatrix lane address bases
    const uint32_t Abase = smb + OFF_A + (wty * 16 + (l & 15)) * ARS + ((l >> 4) << 4);
    const uint32_t Bloff = (uint32_t)((l & 15) * BRS + wtx * 32 + ((l >> 4) << 4));

    double lossLocal = 0.0;
    float bd0 = 3.4e38f, bd1 = 3.4e38f;
    int   bi0 = 0, bi1 = 0;

    for (int g = 0; g < NG2; ++g) {
        const int s = g >> 5, c = g & 31;
        asm volatile("cp.async.wait_group 0;\n");
        __syncthreads();   // chunk g visible; everyone done with the other buffer

        if (g + 1 < NG2)
            prefetch_chunk(g + 1, smb + (((g + 1) & 1) ? OFF_B1 : OFF_B0), tid);

        const uint32_t Bb = smb + ((g & 1) ? OFF_B1 : OFF_B0) + Bloff;

        float ac0[4] = {0.f, 0.f, 0.f, 0.f};
        float ac1[4] = {0.f, 0.f, 0.f, 0.f};

#pragma unroll 4
        for (int ks = 0; ks < 16; ++ks) {
            uint32_t a0[4], a1[4], a2[4], p0[4], p1[4], p2[4];
            LDSM4(a0, Abase + ks * 32);
            LDSM4(a1, Abase + APLANE + ks * 32);
            LDSM4(a2, Abase + 2 * APLANE + ks * 32);
            LDSM4T(p0, Bb + ks * 16 * BRS);
            LDSM4T(p1, Bb + BPLANE + ks * 16 * BRS);
            LDSM4T(p2, Bb + 2 * BPLANE + ks * 16 * BRS);
            // 6 terms, fixed order (deterministic fp32 accumulation)
            MMA(ac0, a0, p0[0], p0[1]);  MMA(ac1, a0, p0[2], p0[3]);
            MMA(ac0, a0, p1[0], p1[1]);  MMA(ac1, a0, p1[2], p1[3]);
            MMA(ac0, a1, p0[0], p0[1]);  MMA(ac1, a1, p0[2], p0[3]);
            MMA(ac0, a0, p2[0], p2[1]);  MMA(ac1, a0, p2[2], p2[3]);
            MMA(ac0, a1, p1[0], p1[1]);  MMA(ac1, a1, p1[2], p1[3]);
            MMA(ac0, a2, p0[0], p0[1]);  MMA(ac1, a2, p0[2], p0[3]);
        }

        // ---- distances + running argmin ----
        // D-frag: rows = tokens wty*16 + {l>>2, l>>2+8}; cols = bins
        //   ac0: bins binb, binb+1;  ac1: bins binb+8, binb+9
        {
            const float* csq = g_cbsq + s * BINS + c * NBIN + wtx * 16 + 2 * (l & 3);
            float q0 = __ldg(csq), q1 = __ldg(csq + 1);
            float q8 = __ldg(csq + 8), q9 = __ldg(csq + 9);
            int binb = c * NBIN + wtx * 16 + 2 * (l & 3);
            if (c == 0) { bd0 = bd1 = 3.4e38f; bi0 = bi1 = 0; }
            float d;
            d = fmaf(-2.f, ac0[0], q0); if (d < bd0) { bd0 = d; bi0 = binb; }
            d = fmaf(-2.f, ac0[1], q1); if (d < bd0) { bd0 = d; bi0 = binb + 1; }
            d = fmaf(-2.f, ac1[0], q8); if (d < bd0) { bd0 = d; bi0 = binb + 8; }
            d = fmaf(-2.f, ac1[1], q9); if (d < bd0) { bd0 = d; bi0 = binb + 9; }
            d = fmaf(-2.f, ac0[2], q0); if (d < bd1) { bd1 = d; bi1 = binb; }
            d = fmaf(-2.f, ac0[3], q1); if (d < bd1) { bd1 = d; bi1 = binb + 1; }
            d = fmaf(-2.f, ac1[2], q8); if (d < bd1) { bd1 = d; bi1 = binb + 8; }
            d = fmaf(-2.f, ac1[3], q9); if (d < bd1) { bd1 = d; bi1 = binb + 9; }
        }

        // ---- stage tail ----
        if (c == NCH - 1) {
            // lexicographic reduce across the 4 lanes of each row group
#pragma unroll
            for (int o = 1; o < 4; o <<= 1) {
                float od0 = __shfl_xor_sync(0xffffffffu, bd0, o);
                int   oi0 = __shfl_xor_sync(0xffffffffu, bi0, o);
                if (od0 < bd0 || (od0 == bd0 && oi0 < bi0)) { bd0 = od0; bi0 = oi0; }
                float od1 = __shfl_xor_sync(0xffffffffu, bd1, o);
                int   oi1 = __shfl_xor_sync(0xffffffffu, bi1, o);
                if (od1 < bd1 || (od1 == bd1 && oi1 < bi1)) { bd1 = od1; bi1 = oi1; }
            }
            if ((l & 3) == 0) {
                int tok = wty * 16 + (l >> 2);
                sRd[wtx * 64 + tok]     = bd0;  sRi[wtx * 64 + tok]     = bi0;
                sRd[wtx * 64 + tok + 8] = bd1;  sRi[wtx * 64 + tok + 8] = bi1;
            }
            __syncthreads();
            if (tid < TT) {
                float d0 = sRd[tid], d1 = sRd[64 + tid];
                int   i0 = sRi[tid], i1 = sRi[64 + tid];
                int idx = (d1 < d0 || (d1 == d0 && i1 < i0)) ? i1 : i0;
                sIdx[tid] = idx;
                out_c[(size_t)(s * BDIM + b) * TDIM + t0 + tid] = (float)idx;
            }
            __syncthreads();

            // ---- residual update: r = (p0+p1+p2) - c[idx]; loss; resplit ----
            {
                int t  = tid >> 2;
                int ko = (tid & 3) * 64;
                int idx = sIdx[t];
                const float* crow = cbs + ((size_t)s * BINS + idx) * DDIM + ko;
                unsigned char* P0 = smraw + OFF_A + t * ARS + ko * 2;
                float lsum = 0.f;
#pragma unroll 8
                for (int k = 0; k < 64; k += 2) {
                    uint32_t u0 = *(uint32_t*)(P0 + k * 2);
                    uint32_t u1 = *(uint32_t*)(P0 + APLANE + k * 2);
                    uint32_t u2 = *(uint32_t*)(P0 + 2 * APLANE + k * 2);
                    float rl = bflo(u0) + bflo(u1) + bflo(u2);
                    float rh = bfhi(u0) + bfhi(u1) + bfhi(u2);
                    float nl = rl - __ldg(crow + k);
                    float nh = rh - __ldg(crow + k + 1);
                    lsum += nl * nl + nh * nh;
                    if (s < NQ - 1) {
                        __nv_bfloat16 h0, h1, h2, g0h, g1h, g2h;
                        split3s(nl, h0, h1, h2);
                        split3s(nh, g0h, g1h, g2h);
                        *(uint32_t*)(P0 + k * 2) =
                            (uint32_t)__bfloat16_as_ushort(h0) | ((uint32_t)__bfloat16_as_ushort(g0h) << 16);
                        *(uint32_t*)(P0 + APLANE + k * 2) =
                            (uint32_t)__bfloat16_as_ushort(h1) | ((uint32_t)__bfloat16_as_ushort(g1h) << 16);
                        *(uint32_t*)(P0 + 2 * APLANE + k * 2) =
                            (uint32_t)__bfloat16_as_ushort(h2) | ((uint32_t)__bfloat16_as_ushort(g2h) << 16);
                    } else {
                        const float* xp = x + (size_t)(b * DDIM + ko + k) * TDIM + t0 + t;
                        float* qp = out_q + (size_t)(b * DDIM + ko + k) * TDIM + t0 + t;
                        qp[0]    = xp[0] - nl;
                        qp[TDIM] = xp[TDIM] - nh;
                    }
                }
                lossLocal += (double)lsum;
            }
            // next iteration's top __syncthreads orders A-plane writes before GEMM
        }
    }
    __syncthreads();

    // ---- per-CTA loss partial (deterministic) ----
#pragma unroll
    for (int o = 16; o; o >>= 1) lossLocal += __shfl_down_sync(0xffffffffu, lossLocal, o);
    if (l == 0) sWD[w] = lossLocal;
    __syncthreads();
    if (tid == 0) {
        double t = 0.0;
#pragma unroll
        for (int i = 0; i < 8; ++i) t += sWD[i];
        g_losspart[blockIdx.x] = t;
        __threadfence();
        unsigned old = atomicAdd(&g_ctr, 1u);
        *sFlg = (old == NTILE - 1) ? 1 : 0;
    }
    __syncthreads();

    // ---- last CTA finalizes scalars ----
    if (*sFlg && tid < 32) {
        __threadfence();
        double ssum = 0.0;
        for (int i = l; i < NTILE; i += 32) ssum += __ldcg(&g_losspart[i]);
#pragma unroll
        for (int o = 16; o; o >>= 1) ssum += __shfl_down_sync(0xffffffffu, ssum, o);
        if (l == 0) {
            int iv = *srp;
            float fv = __int_as_float(iv);
            double sr = (iv > 0 && iv < 100000000) ? (double)iv : (double)fv;
            out[QELEMS + CELEMS]     = (float)((double)NQ * 10.0 * sr / 1000.0);
            out[QELEMS + CELEMS + 1] = (float)(ssum / (4.0 * (double)NQ * (double)QELEMS));
            atomicExch(&g_ctr, 0u);
        }
    }
}

// ---------------------------------------------------------------------------
extern "C" void kernel_launch(void* const* d_in, const int* in_sizes, int n_in,
                              void* d_out, int out_size) {
    const float* x   = nullptr;
    const float* cbs = nullptr;
    const int*   srp = nullptr;
    for (int i = 0; i < n_in; ++i) {
        if (in_sizes[i] == QELEMS)                x   = (const float*)d_in[i];
        else if (in_sizes[i] == NQ * BINS * DDIM) cbs = (const float*)d_in[i];
        else                                      srp = (const int*)d_in[i];
    }
    float* out = (float*)d_out;

    cudaFuncSetAttribute(rvq_main, cudaFuncAttributeMaxDynamicSharedMemorySize, SMEM_BYTES);

    cbsq_kernel<<<(NQ * BINS * 32) / 256, 256>>>(cbs);
    prep_kernel<<<NG2, 256>>>(cbs);
    rvq_main<<<NTILE, NT, SMEM_BYTES>>>(x, cbs, srp, out);
}